// round 16
// baseline (speedup 1.0000x reference)
#include <cuda_runtime.h>
#include <cstdint>

// Problem dims
#define BB 4
#define SS 2048
#define DD 1024
#define HH 64
#define MTOT (BB * SS)   // 8192

// Scratch (device globals — no allocation allowed)
__device__ float g_q [MTOT * HH];
__device__ float g_k [MTOT * HH];
__device__ float g_xv[MTOT * HH];
__device__ float g_x [(size_t)MTOT * DD];     // tf32-clean after xo
__device__ float g_P [(size_t)BB * SS * SS];  // tf32-clean unnormalized E after softmax
__device__ float g_inv[MTOT];                 // per-row 1/sum

__device__ __forceinline__ uint32_t f2tf32(float f) {
    uint32_t u;
    asm("cvt.rna.tf32.f32 %0, %1;" : "=r"(u) : "f"(f));
    return u;
}
__device__ __forceinline__ void split_tf32(float v, float& h, float& l) {
    uint32_t hu; asm("cvt.rna.tf32.f32 %0, %1;" : "=r"(hu) : "f"(v));
    h = __uint_as_float(hu);
    float r = v - h;
    uint32_t lu; asm("cvt.rna.tf32.f32 %0, %1;" : "=r"(lu) : "f"(r));
    l = __uint_as_float(lu);
}
__device__ __forceinline__ void mma_tf32(float* c, const uint32_t* a, const uint32_t* b) {
    asm volatile("mma.sync.aligned.m16n8k8.row.col.f32.tf32.tf32.f32 "
        "{%0,%1,%2,%3}, {%4,%5,%6,%7}, {%8,%9}, {%0,%1,%2,%3};"
        : "+f"(c[0]), "+f"(c[1]), "+f"(c[2]), "+f"(c[3])
        : "r"(a[0]), "r"(a[1]), "r"(a[2]), "r"(a[3]), "r"(b[0]), "r"(b[1]));
}

// ---------------------------------------------------------------------------
// Kernel 1: fused projections via 3xTF32 MMA.  BK 32 -> 64 (halved barriers).
// BM=64, BN=192. 8 warps 2m x 4n; warp tile 32x48. Same per-element k order.
// ---------------------------------------------------------------------------
#define PJ_XS 68
#define PJ_WS 200
__global__ void __launch_bounds__(256) proj_mma_kernel(
    const float* __restrict__ X,
    const float* __restrict__ Wq,
    const float* __restrict__ Wk,
    const float* __restrict__ Wv)
{
    extern __shared__ float sm[];
    float* Xh = sm;                    // [64][68]
    float* Xl = Xh + 64 * PJ_XS;
    float* Wh = Xl + 64 * PJ_XS;       // [64][200] (192 used)
    float* Wl = Wh + 64 * PJ_WS;

    const int tid = threadIdx.x;
    const int m0  = blockIdx.x * 64;
    const float* Ws[3] = {Wq, Wk, Wv};

    const int lane = tid & 31, wid = tid >> 5;
    const int wm = wid >> 2;
    const int wn = wid & 3;
    const int lr = lane >> 2, lc = lane & 3;

    float acc[2][6][4] = {};

    for (int k0 = 0; k0 < DD; k0 += 64) {
        // X tile 64x64 (1024 float4, 4/thread)
        #pragma unroll
        for (int i = 0; i < 4; i++) {
            int idx = tid + i * 256;
            int r = idx >> 4, c = (idx & 15) * 4;
            float4 v = *(const float4*)(X + (size_t)(m0 + r) * DD + k0 + c);
            float4 h, l;
            split_tf32(v.x, h.x, l.x); split_tf32(v.y, h.y, l.y);
            split_tf32(v.z, h.z, l.z); split_tf32(v.w, h.w, l.w);
            *(float4*)(Xh + r * PJ_XS + c) = h;
            *(float4*)(Xl + r * PJ_XS + c) = l;
        }
        // W tiles: 3 x (64x64) into columns z*64 (1024 float4 each, 4/thread)
        #pragma unroll
        for (int z = 0; z < 3; z++) {
            const float* W = Ws[z];
            #pragma unroll
            for (int i = 0; i < 4; i++) {
                int idx = tid + i * 256;
                int r = idx >> 4, c = (idx & 15) * 4;
                float4 v = *(const float4*)(W + (size_t)(k0 + r) * HH + c);
                float4 h, l;
                split_tf32(v.x, h.x, l.x); split_tf32(v.y, h.y, l.y);
                split_tf32(v.z, h.z, l.z); split_tf32(v.w, h.w, l.w);
                *(float4*)(Wh + r * PJ_WS + z * 64 + c) = h;
                *(float4*)(Wl + r * PJ_WS + z * 64 + c) = l;
            }
        }
        __syncthreads();

        #pragma unroll
        for (int ks = 0; ks < 64; ks += 8) {
            uint32_t ah[2][4], al[2][4];
            #pragma unroll
            for (int mt = 0; mt < 2; mt++) {
                int mrow = wm * 32 + mt * 16 + lr;
                ah[mt][0] = __float_as_uint(Xh[(mrow    ) * PJ_XS + ks + lc    ]);
                ah[mt][1] = __float_as_uint(Xh[(mrow + 8) * PJ_XS + ks + lc    ]);
                ah[mt][2] = __float_as_uint(Xh[(mrow    ) * PJ_XS + ks + lc + 4]);
                ah[mt][3] = __float_as_uint(Xh[(mrow + 8) * PJ_XS + ks + lc + 4]);
                al[mt][0] = __float_as_uint(Xl[(mrow    ) * PJ_XS + ks + lc    ]);
                al[mt][1] = __float_as_uint(Xl[(mrow + 8) * PJ_XS + ks + lc    ]);
                al[mt][2] = __float_as_uint(Xl[(mrow    ) * PJ_XS + ks + lc + 4]);
                al[mt][3] = __float_as_uint(Xl[(mrow + 8) * PJ_XS + ks + lc + 4]);
            }
            uint32_t bh[6][2], bl[6][2];
            #pragma unroll
            for (int nt = 0; nt < 6; nt++) {
                int ncol = wn * 48 + nt * 8 + lr;
                bh[nt][0] = __float_as_uint(Wh[(ks + lc    ) * PJ_WS + ncol]);
                bh[nt][1] = __float_as_uint(Wh[(ks + lc + 4) * PJ_WS + ncol]);
                bl[nt][0] = __float_as_uint(Wl[(ks + lc    ) * PJ_WS + ncol]);
                bl[nt][1] = __float_as_uint(Wl[(ks + lc + 4) * PJ_WS + ncol]);
            }
            #pragma unroll
            for (int mt = 0; mt < 2; mt++)
                #pragma unroll
                for (int nt = 0; nt < 6; nt++) {
                    mma_tf32(acc[mt][nt], ah[mt], bh[nt]);
                    mma_tf32(acc[mt][nt], ah[mt], bl[nt]);
                    mma_tf32(acc[mt][nt], al[mt], bh[nt]);
                }
        }
        __syncthreads();
    }

    float* outs[3] = {g_q, g_k, g_xv};
    #pragma unroll
    for (int mt = 0; mt < 2; mt++) {
        int m = m0 + wm * 32 + mt * 16 + lr;
        #pragma unroll
        for (int nt = 0; nt < 6; nt++) {
            int n = wn * 48 + nt * 8 + lc * 2;
            int z = n >> 6;
            int col = n & 63;
            float2 v0 = {acc[mt][nt][0], acc[mt][nt][1]};
            float2 v1 = {acc[mt][nt][2], acc[mt][nt][3]};
            *(float2*)(outs[z] + (size_t)(m    ) * HH + col) = v0;
            *(float2*)(outs[z] + (size_t)(m + 8) * HH + col) = v1;
        }
    }
}

// ---------------------------------------------------------------------------
// Merged mid-stage kernel: xo role + causal-scores role. (unchanged)
// ---------------------------------------------------------------------------
#define XO_AS 68
#define XO_BS 136
#define N_XO_CTAS   512
#define N_SC_PAIRS  136
#define N_SC_CTAS   (N_SC_PAIRS * BB)

__global__ void __launch_bounds__(256, 1) mid_mma_kernel(const float* __restrict__ O)
{
    extern __shared__ float sm[];
    float* Ah = sm;
    float* Al = Ah + 128 * XO_AS;
    float* Bh = Al + 128 * XO_AS;
    float* Bl = Bh + 64 * XO_BS;

    const int bid = blockIdx.x;
    const int tid = threadIdx.x;
    const int lane = tid & 31, wid = tid >> 5;
    const int wm = wid >> 2, wn = wid & 3;
    const int lr = lane >> 2, lc = lane & 3;

    if (bid < N_XO_CTAS) {
        const int e0 = (bid & 7) * 128;
        const int m0 = (bid >> 3) * 128;

        #pragma unroll
        for (int i = 0; i < 8; i++) {
            int idx = tid + i * 256;
            int r = idx >> 4, c = (idx & 15) * 4;
            float4 v = *(const float4*)(g_xv + (size_t)(m0 + r) * HH + c);
            float4 h, l;
            split_tf32(v.x, h.x, l.x); split_tf32(v.y, h.y, l.y);
            split_tf32(v.z, h.z, l.z); split_tf32(v.w, h.w, l.w);
            *(float4*)(Ah + r * XO_AS + c) = h;
            *(float4*)(Al + r * XO_AS + c) = l;
        }
        #pragma unroll
        for (int i = 0; i < 8; i++) {
            int idx = tid + i * 256;
            int e = idx & 127, hc = (idx >> 7) * 4;
            float4 v = *(const float4*)(O + (size_t)(e0 + e) * HH + hc);
            float hx, lx;
            split_tf32(v.x, hx, lx); Bh[(hc + 0) * XO_BS + e] = hx; Bl[(hc + 0) * XO_BS + e] = lx;
            split_tf32(v.y, hx, lx); Bh[(hc + 1) * XO_BS + e] = hx; Bl[(hc + 1) * XO_BS + e] = lx;
            split_tf32(v.z, hx, lx); Bh[(hc + 2) * XO_BS + e] = hx; Bl[(hc + 2) * XO_BS + e] = lx;
            split_tf32(v.w, hx, lx); Bh[(hc + 3) * XO_BS + e] = hx; Bl[(hc + 3) * XO_BS + e] = lx;
        }
        __syncthreads();

        float acc[4][4][4] = {};

        #pragma unroll
        for (int ks = 0; ks < 64; ks += 8) {
            uint32_t ah[4][4], al[4][4], bf[4][2];
            #pragma unroll
            for (int mt = 0; mt < 4; mt++) {
                int mrow = wm * 64 + mt * 16 + lr;
                ah[mt][0] = __float_as_uint(Ah[(mrow    ) * XO_AS + ks + lc    ]);
                ah[mt][1] = __float_as_uint(Ah[(mrow + 8) * XO_AS + ks + lc    ]);
                ah[mt][2] = __float_as_uint(Ah[(mrow    ) * XO_AS + ks + lc + 4]);
                ah[mt][3] = __float_as_uint(Ah[(mrow + 8) * XO_AS + ks + lc + 4]);
                al[mt][0] = __float_as_uint(Al[(mrow    ) * XO_AS + ks + lc    ]);
                al[mt][1] = __float_as_uint(Al[(mrow + 8) * XO_AS + ks + lc    ]);
                al[mt][2] = __float_as_uint(Al[(mrow    ) * XO_AS + ks + lc + 4]);
                al[mt][3] = __float_as_uint(Al[(mrow + 8) * XO_AS + ks + lc + 4]);
            }
            #pragma unroll
            for (int nt = 0; nt < 4; nt++) {
                int ncol = wn * 32 + nt * 8 + lr;
                bf[nt][0] = __float_as_uint(Bh[(ks + lc    ) * XO_BS + ncol]);
                bf[nt][1] = __float_as_uint(Bh[(ks + lc + 4) * XO_BS + ncol]);
            }
            #pragma unroll
            for (int mt = 0; mt < 4; mt++)
                #pragma unroll
                for (int nt = 0; nt < 4; nt++) {
                    mma_tf32(acc[mt][nt], ah[mt], bf[nt]);
                    mma_tf32(acc[mt][nt], al[mt], bf[nt]);
                }
            #pragma unroll
            for (int nt = 0; nt < 4; nt++) {
                int ncol = wn * 32 + nt * 8 + lr;
                bf[nt][0] = __float_as_uint(Bl[(ks + lc    ) * XO_BS + ncol]);
                bf[nt][1] = __float_as_uint(Bl[(ks + lc + 4) * XO_BS + ncol]);
            }
            #pragma unroll
            for (int mt = 0; mt < 4; mt++)
                #pragma unroll
                for (int nt = 0; nt < 4; nt++)
                    mma_tf32(acc[mt][nt], ah[mt], bf[nt]);
        }

        #pragma unroll
        for (int mt = 0; mt < 4; mt++) {
            int m = m0 + wm * 64 + mt * 16 + lr;
            #pragma unroll
            for (int nt = 0; nt < 4; nt++) {
                int n = e0 + wn * 32 + nt * 8 + lc * 2;
                float2 v0 = {__uint_as_float(f2tf32(acc[mt][nt][0])),
                             __uint_as_float(f2tf32(acc[mt][nt][1]))};
                float2 v1 = {__uint_as_float(f2tf32(acc[mt][nt][2])),
                             __uint_as_float(f2tf32(acc[mt][nt][3]))};
                *(float2*)(g_x + (size_t)(m    ) * DD + n) = v0;
                *(float2*)(g_x + (size_t)(m + 8) * DD + n) = v1;
            }
        }
    } else {
        const int sp = bid - N_XO_CTAS;
        const int b  = sp / N_SC_PAIRS;
        const int p  = sp - b * N_SC_PAIRS;
        int it = (int)((sqrtf(8.0f * (float)p + 1.0f) - 1.0f) * 0.5f);
        while ((it + 1) * (it + 2) / 2 <= p) it++;
        while (it * (it + 1) / 2 > p)        it--;
        const int jt = p - it * (it + 1) / 2;

        const int i0 = it * 128, j0 = jt * 128;
        const int base = b * SS;

        #pragma unroll
        for (int i = 0; i < 8; i++) {
            int idx = tid + i * 256;
            int r = idx >> 4, c = (idx & 15) * 4;
            float4 v = *(const float4*)(g_q + (size_t)(base + i0 + r) * HH + c);
            float4 h, l;
            split_tf32(v.x, h.x, l.x); split_tf32(v.y, h.y, l.y);
            split_tf32(v.z, h.z, l.z); split_tf32(v.w, h.w, l.w);
            *(float4*)(Ah + r * XO_AS + c) = h;
            *(float4*)(Al + r * XO_AS + c) = l;
        }
        #pragma unroll
        for (int i = 0; i < 8; i++) {
            int idx = tid + i * 256;
            int j = idx & 127, hc = (idx >> 7) * 4;
            float4 v = *(const float4*)(g_k + (size_t)(base + j0 + j) * HH + hc);
            float hx, lx;
            split_tf32(v.x, hx, lx); Bh[(hc + 0) * XO_BS + j] = hx; Bl[(hc + 0) * XO_BS + j] = lx;
            split_tf32(v.y, hx, lx); Bh[(hc + 1) * XO_BS + j] = hx; Bl[(hc + 1) * XO_BS + j] = lx;
            split_tf32(v.z, hx, lx); Bh[(hc + 2) * XO_BS + j] = hx; Bl[(hc + 2) * XO_BS + j] = lx;
            split_tf32(v.w, hx, lx); Bh[(hc + 3) * XO_BS + j] = hx; Bl[(hc + 3) * XO_BS + j] = lx;
        }
        __syncthreads();

        float acc[4][4][4] = {};

        #pragma unroll
        for (int ks = 0; ks < 64; ks += 8) {
            uint32_t ah[4][4], al[4][4], bf[4][2];
            #pragma unroll
            for (int mt = 0; mt < 4; mt++) {
                int mrow = wm * 64 + mt * 16 + lr;
                ah[mt][0] = __float_as_uint(Ah[(mrow    ) * XO_AS + ks + lc    ]);
                ah[mt][1] = __float_as_uint(Ah[(mrow + 8) * XO_AS + ks + lc    ]);
                ah[mt][2] = __float_as_uint(Ah[(mrow    ) * XO_AS + ks + lc + 4]);
                ah[mt][3] = __float_as_uint(Ah[(mrow + 8) * XO_AS + ks + lc + 4]);
                al[mt][0] = __float_as_uint(Al[(mrow    ) * XO_AS + ks + lc    ]);
                al[mt][1] = __float_as_uint(Al[(mrow + 8) * XO_AS + ks + lc    ]);
                al[mt][2] = __float_as_uint(Al[(mrow    ) * XO_AS + ks + lc + 4]);
                al[mt][3] = __float_as_uint(Al[(mrow + 8) * XO_AS + ks + lc + 4]);
            }
            #pragma unroll
            for (int nt = 0; nt < 4; nt++) {
                int ncol = wn * 32 + nt * 8 + lr;
                bf[nt][0] = __float_as_uint(Bh[(ks + lc    ) * XO_BS + ncol]);
                bf[nt][1] = __float_as_uint(Bh[(ks + lc + 4) * XO_BS + ncol]);
            }
            #pragma unroll
            for (int mt = 0; mt < 4; mt++)
                #pragma unroll
                for (int nt = 0; nt < 4; nt++) {
                    mma_tf32(acc[mt][nt], ah[mt], bf[nt]);
                    mma_tf32(acc[mt][nt], al[mt], bf[nt]);
                }
            #pragma unroll
            for (int nt = 0; nt < 4; nt++) {
                int ncol = wn * 32 + nt * 8 + lr;
                bf[nt][0] = __float_as_uint(Bl[(ks + lc    ) * XO_BS + ncol]);
                bf[nt][1] = __float_as_uint(Bl[(ks + lc + 4) * XO_BS + ncol]);
            }
            #pragma unroll
            for (int mt = 0; mt < 4; mt++)
                #pragma unroll
                for (int nt = 0; nt < 4; nt++)
                    mma_tf32(acc[mt][nt], ah[mt], bf[nt]);
        }

        float* Pb = g_P + (size_t)b * SS * SS;
        if (jt < it) {
            #pragma unroll
            for (int mt = 0; mt < 4; mt++) {
                int gi = i0 + wm * 64 + mt * 16 + lr;
                #pragma unroll
                for (int nt = 0; nt < 4; nt++) {
                    int gj = j0 + wn * 32 + nt * 8 + lc * 2;
                    float2 v0 = {acc[mt][nt][0], acc[mt][nt][1]};
                    float2 v1 = {acc[mt][nt][2], acc[mt][nt][3]};
                    *(float2*)(Pb + (size_t)(gi    ) * SS + gj) = v0;
                    *(float2*)(Pb + (size_t)(gi + 8) * SS + gj) = v1;
                }
            }
        } else {
            #pragma unroll
            for (int mt = 0; mt < 4; mt++) {
                int gi = i0 + wm * 64 + mt * 16 + lr;
                #pragma unroll
                for (int nt = 0; nt < 4; nt++) {
                    int gj = j0 + wn * 32 + nt * 8 + lc * 2;
                    if (gj     <= gi    ) Pb[(size_t)(gi    ) * SS + gj    ] = acc[mt][nt][0];
                    if (gj + 1 <= gi    ) Pb[(size_t)(gi    ) * SS + gj + 1] = acc[mt][nt][1];
                    if (gj     <= gi + 8) Pb[(size_t)(gi + 8) * SS + gj    ] = acc[mt][nt][2];
                    if (gj + 1 <= gi + 8) Pb[(size_t)(gi + 8) * SS + gj + 1] = acc[mt][nt][3];
                }
            }
        }
    }
}

// ---------------------------------------------------------------------------
// Kernel 4: row softmax, 2 passes, unnormalized tf32(E) + g_inv. (unchanged)
// ---------------------------------------------------------------------------
__global__ void __launch_bounds__(256) softmax_kernel()
{
    const int g = blockIdx.x;
    const int q = g & (SS - 1);
    float* row = g_P + (size_t)g * SS;
    const int len  = q + 1;
    const int len4 = len & ~3;
    const int kend = ((q >> 7) + 1) << 7;

    __shared__ float buf[SS];
    __shared__ float red[8];
    const int tid  = threadIdx.x;
    const int lane = tid & 31, wid = tid >> 5;

    float mx = -3.0e38f;
    for (int i = tid * 4; i < len4; i += 1024) {
        float4 v = *(const float4*)(row + i);
        *(float4*)(buf + i) = v;
        mx = fmaxf(fmaxf(fmaxf(mx, v.x), v.y), fmaxf(v.z, v.w));
    }
    for (int i = len4 + tid; i < len; i += 256) {
        float v = row[i];
        buf[i] = v;
        mx = fmaxf(mx, v);
    }
    #pragma unroll
    for (int o = 16; o > 0; o >>= 1) mx = fmaxf(mx, __shfl_xor_sync(0xffffffffu, mx, o));
    if (lane == 0) red[wid] = mx;
    __syncthreads();
    float m = fmaxf(fmaxf(fmaxf(red[0], red[1]), fmaxf(red[2], red[3])),
                    fmaxf(fmaxf(red[4], red[5]), fmaxf(red[6], red[7])));
    __syncthreads();

    float sm = 0.f;
    for (int i = tid * 4; i < len4; i += 1024) {
        float4 v = *(const float4*)(buf + i);
        v.x = __expf(v.x - m); v.y = __expf(v.y - m);
        v.z = __expf(v.z - m); v.w = __expf(v.w - m);
        sm += (v.x + v.y) + (v.z + v.w);
        v.x = __uint_as_float(f2tf32(v.x));
        v.y = __uint_as_float(f2tf32(v.y));
        v.z = __uint_as_float(f2tf32(v.z));
        v.w = __uint_as_float(f2tf32(v.w));
        *(float4*)(row + i) = v;
    }
    for (int i = len4 + tid; i < len; i += 256) {
        float e = __expf(buf[i] - m);
        sm += e;
        row[i] = __uint_as_float(f2tf32(e));
    }
    #pragma unroll
    for (int o = 16; o > 0; o >>= 1) sm += __shfl_xor_sync(0xffffffffu, sm, o);
    if (lane == 0) red[wid] = sm;
    __syncthreads();
    if (tid == 0) {
        g_inv[g] = 1.0f / (((red[0] + red[1]) + (red[2] + red[3])) +
                           ((red[4] + red[5]) + (red[6] + red[7])));
    }

    for (int i = len + tid; i < kend; i += 256)
        row[i] = 0.0f;
}

// ---------------------------------------------------------------------------
// Kernel 5: out[b] = diag(inv) * (E[b] @ x[b]).  BM=128, BN=256, BK=64.
// 512 threads, 16 warps 4m x 4n, warp tile 32x64. 2-stage double buffer
// (204.8 KB smem, occ 1 — proven irrelevant). Barriers per SM halved again.
// k-accumulation order per output element unchanged -> bit-identical result.
// ---------------------------------------------------------------------------
#define PV_STAGES 2
#define PV_AS 68
#define PV_BS 264
#define PV_STAGE_FLOATS (128 * PV_AS + 64 * PV_BS)   // 8704 + 16896 = 25600

__global__ void __launch_bounds__(512, 1) pv_mma_kernel(float* __restrict__ out)
{
    extern __shared__ float sm[];

    const int tid = threadIdx.x;
    const int n0 = blockIdx.x * 256;
    const int m0 = ((int)gridDim.y - 1 - (int)blockIdx.y) * 128;   // LPT
    const int b  = blockIdx.z;

    const float* P  = g_P + (size_t)b * SS * SS;
    const float* Xb = g_x + (size_t)b * SS * DD;
    const int ntiles = (m0 + 128) / 64;     // BK=64 -> >= 2 always

    auto issue_tile = [&](int t) {
        const int stg = t % PV_STAGES;
        float* As = sm + stg * PV_STAGE_FLOATS;
        float* Bs = As + 128 * PV_AS;
        const int kt = t * 64;
        #pragma unroll
        for (int i = 0; i < 4; i++) {            // A: 128x64 = 2048 float4
            int idx = tid + i * 512;
            int r = idx >> 4, c = (idx & 15) * 4;
            const float* src = P + (size_t)(m0 + r) * SS + kt + c;
            uint32_t dst = (uint32_t)__cvta_generic_to_shared(As + r * PV_AS + c);
            asm volatile("cp.async.cg.shared.global [%0], [%1], 16;\n"
                         :: "r"(dst), "l"(src) : "memory");
        }
        #pragma unroll
        for (int i = 0; i < 8; i++) {            // B: 64x256 = 4096 float4
            int idx = tid + i * 512;
            int r = idx >> 6, c = (idx & 63) * 4;
            const float* src = Xb + (size_t)(kt + r) * DD + n0 + c;
            uint32_t dst = (uint32_t)__cvta_generic_to_shared(Bs + r * PV_BS + c);
            asm volatile("cp.async.cg.shared.global [%0], [%1], 16;\n"
                         :: "r"(dst), "l"(src) : "memory");
        }
    };

    #pragma unroll
    for (int t = 0; t < PV_STAGES - 1; t++) {
        issue_tile(t);                            // ntiles >= 2 always
        asm volatile("cp.async.commit_group;\n" ::: "memory");
    }

    const int lane = tid & 31, wid = tid >> 5;
    const int wm = wid >> 2, wn = wid & 3;        // 4x4 warps
    const int lr = lane >> 2, lc = lane & 3;

    float acc[2][8][4] = {};                      // warp tile 32x64

    for (int t = 0; t < ntiles; t++) {
        asm volatile("cp.async.wait_group %0;\n" :: "n"(PV_STAGES - 2) : "memory");
        __syncthreads();
        if (t + PV_STAGES - 1 < ntiles) issue_tile(t + PV_STAGES - 1);
        asm volatile("cp.async.commit_group;\n" ::: "memory");

        const int stg = t % PV_STAGES;
        const float* As = sm + stg * PV_STAGE_FLOATS;
        const float* Bs = As + 128 * PV_AS;

        #pragma unroll
        for (int ks = 0; ks < 64; ks += 8) {
            uint32_t afrag[2][4];
            #pragma unroll
            for (int mt = 0; mt < 2; mt++) {
                int mrow = wm * 32 + mt * 16 + lr;
                afrag[mt][0] = __float_as_uint(As[(mrow    ) * PV_AS + ks + lc    ]);
                afrag[mt][1] = __float_as_uint(As[(mrow + 8) * PV_AS + ks + lc    ]);
                afrag[mt][2] = __float_as_uint(As[(mrow    ) * PV_AS + ks + lc + 4]);
                afrag[mt][3] = __float_as_uint(As[(mrow + 8) * PV_AS + ks + lc + 4]);
            }
            uint32_t bfrag[8][2];
            #pragma unroll
            for (int nt = 0; nt < 8; nt++) {
                int ncol = wn * 64 + nt * 8 + lr;
                bfrag[nt][0] = __float_as_uint(Bs[(ks + lc    ) * PV_BS + ncol]);
                bfrag[nt][1] = __float_as_uint(Bs[(ks + lc + 4) * PV_BS + ncol]);
            }
            #pragma unroll
            for (int mt = 0; mt < 2; mt++)
                #pragma unroll
                for (int nt = 0; nt < 8; nt++)
                    mma_tf32(acc[mt][nt], afrag[mt], bfrag[nt]);
        }
    }

    #pragma unroll
    for (int mt = 0; mt < 2; mt++) {
        int m = m0 + wm * 32 + mt * 16 + lr;
        float inv0 = g_inv[b * SS + m];
        float inv1 = g_inv[b * SS + m + 8];
        #pragma unroll
        for (int nt = 0; nt < 8; nt++) {
            int n = n0 + wn * 64 + nt * 8 + lc * 2;
            float2 v0 = {acc[mt][nt][0] * inv0, acc[mt][nt][1] * inv0};
            float2 v1 = {acc[mt][nt][2] * inv1, acc[mt][nt][3] * inv1};
            *(float2*)(out + (size_t)(b * SS + m    ) * DD + n) = v0;
            *(float2*)(out + (size_t)(b * SS + m + 8) * DD + n) = v1;
        }
    }
}

// ---------------------------------------------------------------------------
// Host launch (graph-capturable: kernel launches only)
// ---------------------------------------------------------------------------
extern "C" void kernel_launch(void* const* d_in, const int* in_sizes, int n_in,
                              void* d_out, int out_size)
{
    const float* X  = (const float*)d_in[0];
    const float* Wq = (const float*)d_in[1];
    const float* Wk = (const float*)d_in[2];
    const float* Wv = (const float*)d_in[3];
    const float* Wo = (const float*)d_in[4];
    float* out = (float*)d_out;

    const int pj_smem  = (2 * 64 * PJ_XS + 2 * 64 * PJ_WS) * 4;    // 137,216
    const int mid_smem = (2 * 128 * XO_AS + 2 * 64 * XO_BS) * 4;   // 139,264
    const int pv_smem  = PV_STAGES * PV_STAGE_FLOATS * 4;          // 204,800

    cudaFuncSetAttribute(proj_mma_kernel, cudaFuncAttributeMaxDynamicSharedMemorySize, pj_smem);
    cudaFuncSetAttribute(mid_mma_kernel,  cudaFuncAttributeMaxDynamicSharedMemorySize, mid_smem);
    cudaFuncSetAttribute(pv_mma_kernel,   cudaFuncAttributeMaxDynamicSharedMemorySize, pv_smem);

    proj_mma_kernel<<<dim3(MTOT / 64, 1, 1), 256, pj_smem>>>(X, Wq, Wk, Wv);
    mid_mma_kernel <<<N_XO_CTAS + N_SC_CTAS, 256, mid_smem>>>(Wo);
    softmax_kernel <<<MTOT, 256>>>();
    pv_mma_kernel  <<<dim3(DD / 256, SS / 128, BB), 512, pv_smem>>>(out);
}

// round 17
// speedup vs baseline: 1.1266x; 1.1266x over previous
#include <cuda_runtime.h>
#include <cstdint>

// Problem dims
#define BB 4
#define SS 2048
#define DD 1024
#define HH 64
#define MTOT (BB * SS)   // 8192

// Scratch (device globals — no allocation allowed)
__device__ float g_q [MTOT * HH];
__device__ float g_k [MTOT * HH];
__device__ float g_xv[MTOT * HH];
__device__ float g_x [(size_t)MTOT * DD];     // tf32-clean after xo
__device__ float g_P [(size_t)BB * SS * SS];  // tf32-clean unnormalized E after softmax
__device__ float g_inv[MTOT];                 // per-row 1/sum

__device__ __forceinline__ uint32_t f2tf32(float f) {
    uint32_t u;
    asm("cvt.rna.tf32.f32 %0, %1;" : "=r"(u) : "f"(f));
    return u;
}
__device__ __forceinline__ void split_tf32(float v, float& h, float& l) {
    uint32_t hu; asm("cvt.rna.tf32.f32 %0, %1;" : "=r"(hu) : "f"(v));
    h = __uint_as_float(hu);
    float r = v - h;
    uint32_t lu; asm("cvt.rna.tf32.f32 %0, %1;" : "=r"(lu) : "f"(r));
    l = __uint_as_float(lu);
}
__device__ __forceinline__ void mma_tf32(float* c, const uint32_t* a, const uint32_t* b) {
    asm volatile("mma.sync.aligned.m16n8k8.row.col.f32.tf32.tf32.f32 "
        "{%0,%1,%2,%3}, {%4,%5,%6,%7}, {%8,%9}, {%0,%1,%2,%3};"
        : "+f"(c[0]), "+f"(c[1]), "+f"(c[2]), "+f"(c[3])
        : "r"(a[0]), "r"(a[1]), "r"(a[2]), "r"(a[3]), "r"(b[0]), "r"(b[1]));
}

// ---------------------------------------------------------------------------
// Kernel 1: fused projections via 3xTF32 MMA.  BK=64 (round-16, proven win).
// BM=64, BN=192. 8 warps 2m x 4n; warp tile 32x48.
// ---------------------------------------------------------------------------
#define PJ_XS 68
#define PJ_WS 200
__global__ void __launch_bounds__(256) proj_mma_kernel(
    const float* __restrict__ X,
    const float* __restrict__ Wq,
    const float* __restrict__ Wk,
    const float* __restrict__ Wv)
{
    extern __shared__ float sm[];
    float* Xh = sm;                    // [64][68]
    float* Xl = Xh + 64 * PJ_XS;
    float* Wh = Xl + 64 * PJ_XS;       // [64][200] (192 used)
    float* Wl = Wh + 64 * PJ_WS;

    const int tid = threadIdx.x;
    const int m0  = blockIdx.x * 64;
    const float* Ws[3] = {Wq, Wk, Wv};

    const int lane = tid & 31, wid = tid >> 5;
    const int wm = wid >> 2;
    const int wn = wid & 3;
    const int lr = lane >> 2, lc = lane & 3;

    float acc[2][6][4] = {};

    for (int k0 = 0; k0 < DD; k0 += 64) {
        #pragma unroll
        for (int i = 0; i < 4; i++) {
            int idx = tid + i * 256;
            int r = idx >> 4, c = (idx & 15) * 4;
            float4 v = *(const float4*)(X + (size_t)(m0 + r) * DD + k0 + c);
            float4 h, l;
            split_tf32(v.x, h.x, l.x); split_tf32(v.y, h.y, l.y);
            split_tf32(v.z, h.z, l.z); split_tf32(v.w, h.w, l.w);
            *(float4*)(Xh + r * PJ_XS + c) = h;
            *(float4*)(Xl + r * PJ_XS + c) = l;
        }
        #pragma unroll
        for (int z = 0; z < 3; z++) {
            const float* W = Ws[z];
            #pragma unroll
            for (int i = 0; i < 4; i++) {
                int idx = tid + i * 256;
                int r = idx >> 4, c = (idx & 15) * 4;
                float4 v = *(const float4*)(W + (size_t)(k0 + r) * HH + c);
                float4 h, l;
                split_tf32(v.x, h.x, l.x); split_tf32(v.y, h.y, l.y);
                split_tf32(v.z, h.z, l.z); split_tf32(v.w, h.w, l.w);
                *(float4*)(Wh + r * PJ_WS + z * 64 + c) = h;
                *(float4*)(Wl + r * PJ_WS + z * 64 + c) = l;
            }
        }
        __syncthreads();

        #pragma unroll
        for (int ks = 0; ks < 64; ks += 8) {
            uint32_t ah[2][4], al[2][4];
            #pragma unroll
            for (int mt = 0; mt < 2; mt++) {
                int mrow = wm * 32 + mt * 16 + lr;
                ah[mt][0] = __float_as_uint(Xh[(mrow    ) * PJ_XS + ks + lc    ]);
                ah[mt][1] = __float_as_uint(Xh[(mrow + 8) * PJ_XS + ks + lc    ]);
                ah[mt][2] = __float_as_uint(Xh[(mrow    ) * PJ_XS + ks + lc + 4]);
                ah[mt][3] = __float_as_uint(Xh[(mrow + 8) * PJ_XS + ks + lc + 4]);
                al[mt][0] = __float_as_uint(Xl[(mrow    ) * PJ_XS + ks + lc    ]);
                al[mt][1] = __float_as_uint(Xl[(mrow + 8) * PJ_XS + ks + lc    ]);
                al[mt][2] = __float_as_uint(Xl[(mrow    ) * PJ_XS + ks + lc + 4]);
                al[mt][3] = __float_as_uint(Xl[(mrow + 8) * PJ_XS + ks + lc + 4]);
            }
            uint32_t bh[6][2], bl[6][2];
            #pragma unroll
            for (int nt = 0; nt < 6; nt++) {
                int ncol = wn * 48 + nt * 8 + lr;
                bh[nt][0] = __float_as_uint(Wh[(ks + lc    ) * PJ_WS + ncol]);
                bh[nt][1] = __float_as_uint(Wh[(ks + lc + 4) * PJ_WS + ncol]);
                bl[nt][0] = __float_as_uint(Wl[(ks + lc    ) * PJ_WS + ncol]);
                bl[nt][1] = __float_as_uint(Wl[(ks + lc + 4) * PJ_WS + ncol]);
            }
            #pragma unroll
            for (int mt = 0; mt < 2; mt++)
                #pragma unroll
                for (int nt = 0; nt < 6; nt++) {
                    mma_tf32(acc[mt][nt], ah[mt], bh[nt]);
                    mma_tf32(acc[mt][nt], ah[mt], bl[nt]);
                    mma_tf32(acc[mt][nt], al[mt], bh[nt]);
                }
        }
        __syncthreads();
    }

    float* outs[3] = {g_q, g_k, g_xv};
    #pragma unroll
    for (int mt = 0; mt < 2; mt++) {
        int m = m0 + wm * 32 + mt * 16 + lr;
        #pragma unroll
        for (int nt = 0; nt < 6; nt++) {
            int n = wn * 48 + nt * 8 + lc * 2;
            int z = n >> 6;
            int col = n & 63;
            float2 v0 = {acc[mt][nt][0], acc[mt][nt][1]};
            float2 v1 = {acc[mt][nt][2], acc[mt][nt][3]};
            *(float2*)(outs[z] + (size_t)(m    ) * HH + col) = v0;
            *(float2*)(outs[z] + (size_t)(m + 8) * HH + col) = v1;
        }
    }
}

// ---------------------------------------------------------------------------
// Merged mid-stage kernel: xo role + causal-scores role. (unchanged)
// ---------------------------------------------------------------------------
#define XO_AS 68
#define XO_BS 136
#define N_XO_CTAS   512
#define N_SC_PAIRS  136
#define N_SC_CTAS   (N_SC_PAIRS * BB)

__global__ void __launch_bounds__(256, 1) mid_mma_kernel(const float* __restrict__ O)
{
    extern __shared__ float sm[];
    float* Ah = sm;
    float* Al = Ah + 128 * XO_AS;
    float* Bh = Al + 128 * XO_AS;
    float* Bl = Bh + 64 * XO_BS;

    const int bid = blockIdx.x;
    const int tid = threadIdx.x;
    const int lane = tid & 31, wid = tid >> 5;
    const int wm = wid >> 2, wn = wid & 3;
    const int lr = lane >> 2, lc = lane & 3;

    if (bid < N_XO_CTAS) {
        const int e0 = (bid & 7) * 128;
        const int m0 = (bid >> 3) * 128;

        #pragma unroll
        for (int i = 0; i < 8; i++) {
            int idx = tid + i * 256;
            int r = idx >> 4, c = (idx & 15) * 4;
            float4 v = *(const float4*)(g_xv + (size_t)(m0 + r) * HH + c);
            float4 h, l;
            split_tf32(v.x, h.x, l.x); split_tf32(v.y, h.y, l.y);
            split_tf32(v.z, h.z, l.z); split_tf32(v.w, h.w, l.w);
            *(float4*)(Ah + r * XO_AS + c) = h;
            *(float4*)(Al + r * XO_AS + c) = l;
        }
        #pragma unroll
        for (int i = 0; i < 8; i++) {
            int idx = tid + i * 256;
            int e = idx & 127, hc = (idx >> 7) * 4;
            float4 v = *(const float4*)(O + (size_t)(e0 + e) * HH + hc);
            float hx, lx;
            split_tf32(v.x, hx, lx); Bh[(hc + 0) * XO_BS + e] = hx; Bl[(hc + 0) * XO_BS + e] = lx;
            split_tf32(v.y, hx, lx); Bh[(hc + 1) * XO_BS + e] = hx; Bl[(hc + 1) * XO_BS + e] = lx;
            split_tf32(v.z, hx, lx); Bh[(hc + 2) * XO_BS + e] = hx; Bl[(hc + 2) * XO_BS + e] = lx;
            split_tf32(v.w, hx, lx); Bh[(hc + 3) * XO_BS + e] = hx; Bl[(hc + 3) * XO_BS + e] = lx;
        }
        __syncthreads();

        float acc[4][4][4] = {};

        #pragma unroll
        for (int ks = 0; ks < 64; ks += 8) {
            uint32_t ah[4][4], al[4][4], bf[4][2];
            #pragma unroll
            for (int mt = 0; mt < 4; mt++) {
                int mrow = wm * 64 + mt * 16 + lr;
                ah[mt][0] = __float_as_uint(Ah[(mrow    ) * XO_AS + ks + lc    ]);
                ah[mt][1] = __float_as_uint(Ah[(mrow + 8) * XO_AS + ks + lc    ]);
                ah[mt][2] = __float_as_uint(Ah[(mrow    ) * XO_AS + ks + lc + 4]);
                ah[mt][3] = __float_as_uint(Ah[(mrow + 8) * XO_AS + ks + lc + 4]);
                al[mt][0] = __float_as_uint(Al[(mrow    ) * XO_AS + ks + lc    ]);
                al[mt][1] = __float_as_uint(Al[(mrow + 8) * XO_AS + ks + lc    ]);
                al[mt][2] = __float_as_uint(Al[(mrow    ) * XO_AS + ks + lc + 4]);
                al[mt][3] = __float_as_uint(Al[(mrow + 8) * XO_AS + ks + lc + 4]);
            }
            #pragma unroll
            for (int nt = 0; nt < 4; nt++) {
                int ncol = wn * 32 + nt * 8 + lr;
                bf[nt][0] = __float_as_uint(Bh[(ks + lc    ) * XO_BS + ncol]);
                bf[nt][1] = __float_as_uint(Bh[(ks + lc + 4) * XO_BS + ncol]);
            }
            #pragma unroll
            for (int mt = 0; mt < 4; mt++)
                #pragma unroll
                for (int nt = 0; nt < 4; nt++) {
                    mma_tf32(acc[mt][nt], ah[mt], bf[nt]);
                    mma_tf32(acc[mt][nt], al[mt], bf[nt]);
                }
            #pragma unroll
            for (int nt = 0; nt < 4; nt++) {
                int ncol = wn * 32 + nt * 8 + lr;
                bf[nt][0] = __float_as_uint(Bl[(ks + lc    ) * XO_BS + ncol]);
                bf[nt][1] = __float_as_uint(Bl[(ks + lc + 4) * XO_BS + ncol]);
            }
            #pragma unroll
            for (int mt = 0; mt < 4; mt++)
                #pragma unroll
                for (int nt = 0; nt < 4; nt++)
                    mma_tf32(acc[mt][nt], ah[mt], bf[nt]);
        }

        #pragma unroll
        for (int mt = 0; mt < 4; mt++) {
            int m = m0 + wm * 64 + mt * 16 + lr;
            #pragma unroll
            for (int nt = 0; nt < 4; nt++) {
                int n = e0 + wn * 32 + nt * 8 + lc * 2;
                float2 v0 = {__uint_as_float(f2tf32(acc[mt][nt][0])),
                             __uint_as_float(f2tf32(acc[mt][nt][1]))};
                float2 v1 = {__uint_as_float(f2tf32(acc[mt][nt][2])),
                             __uint_as_float(f2tf32(acc[mt][nt][3]))};
                *(float2*)(g_x + (size_t)(m    ) * DD + n) = v0;
                *(float2*)(g_x + (size_t)(m + 8) * DD + n) = v1;
            }
        }
    } else {
        const int sp = bid - N_XO_CTAS;
        const int b  = sp / N_SC_PAIRS;
        const int p  = sp - b * N_SC_PAIRS;
        int it = (int)((sqrtf(8.0f * (float)p + 1.0f) - 1.0f) * 0.5f);
        while ((it + 1) * (it + 2) / 2 <= p) it++;
        while (it * (it + 1) / 2 > p)        it--;
        const int jt = p - it * (it + 1) / 2;

        const int i0 = it * 128, j0 = jt * 128;
        const int base = b * SS;

        #pragma unroll
        for (int i = 0; i < 8; i++) {
            int idx = tid + i * 256;
            int r = idx >> 4, c = (idx & 15) * 4;
            float4 v = *(const float4*)(g_q + (size_t)(base + i0 + r) * HH + c);
            float4 h, l;
            split_tf32(v.x, h.x, l.x); split_tf32(v.y, h.y, l.y);
            split_tf32(v.z, h.z, l.z); split_tf32(v.w, h.w, l.w);
            *(float4*)(Ah + r * XO_AS + c) = h;
            *(float4*)(Al + r * XO_AS + c) = l;
        }
        #pragma unroll
        for (int i = 0; i < 8; i++) {
            int idx = tid + i * 256;
            int j = idx & 127, hc = (idx >> 7) * 4;
            float4 v = *(const float4*)(g_k + (size_t)(base + j0 + j) * HH + hc);
            float hx, lx;
            split_tf32(v.x, hx, lx); Bh[(hc + 0) * XO_BS + j] = hx; Bl[(hc + 0) * XO_BS + j] = lx;
            split_tf32(v.y, hx, lx); Bh[(hc + 1) * XO_BS + j] = hx; Bl[(hc + 1) * XO_BS + j] = lx;
            split_tf32(v.z, hx, lx); Bh[(hc + 2) * XO_BS + j] = hx; Bl[(hc + 2) * XO_BS + j] = lx;
            split_tf32(v.w, hx, lx); Bh[(hc + 3) * XO_BS + j] = hx; Bl[(hc + 3) * XO_BS + j] = lx;
        }
        __syncthreads();

        float acc[4][4][4] = {};

        #pragma unroll
        for (int ks = 0; ks < 64; ks += 8) {
            uint32_t ah[4][4], al[4][4], bf[4][2];
            #pragma unroll
            for (int mt = 0; mt < 4; mt++) {
                int mrow = wm * 64 + mt * 16 + lr;
                ah[mt][0] = __float_as_uint(Ah[(mrow    ) * XO_AS + ks + lc    ]);
                ah[mt][1] = __float_as_uint(Ah[(mrow + 8) * XO_AS + ks + lc    ]);
                ah[mt][2] = __float_as_uint(Ah[(mrow    ) * XO_AS + ks + lc + 4]);
                ah[mt][3] = __float_as_uint(Ah[(mrow + 8) * XO_AS + ks + lc + 4]);
                al[mt][0] = __float_as_uint(Al[(mrow    ) * XO_AS + ks + lc    ]);
                al[mt][1] = __float_as_uint(Al[(mrow + 8) * XO_AS + ks + lc    ]);
                al[mt][2] = __float_as_uint(Al[(mrow    ) * XO_AS + ks + lc + 4]);
                al[mt][3] = __float_as_uint(Al[(mrow + 8) * XO_AS + ks + lc + 4]);
            }
            #pragma unroll
            for (int nt = 0; nt < 4; nt++) {
                int ncol = wn * 32 + nt * 8 + lr;
                bf[nt][0] = __float_as_uint(Bh[(ks + lc    ) * XO_BS + ncol]);
                bf[nt][1] = __float_as_uint(Bh[(ks + lc + 4) * XO_BS + ncol]);
            }
            #pragma unroll
            for (int mt = 0; mt < 4; mt++)
                #pragma unroll
                for (int nt = 0; nt < 4; nt++) {
                    mma_tf32(acc[mt][nt], ah[mt], bf[nt]);
                    mma_tf32(acc[mt][nt], al[mt], bf[nt]);
                }
            #pragma unroll
            for (int nt = 0; nt < 4; nt++) {
                int ncol = wn * 32 + nt * 8 + lr;
                bf[nt][0] = __float_as_uint(Bl[(ks + lc    ) * XO_BS + ncol]);
                bf[nt][1] = __float_as_uint(Bl[(ks + lc + 4) * XO_BS + ncol]);
            }
            #pragma unroll
            for (int mt = 0; mt < 4; mt++)
                #pragma unroll
                for (int nt = 0; nt < 4; nt++)
                    mma_tf32(acc[mt][nt], ah[mt], bf[nt]);
        }

        float* Pb = g_P + (size_t)b * SS * SS;
        if (jt < it) {
            #pragma unroll
            for (int mt = 0; mt < 4; mt++) {
                int gi = i0 + wm * 64 + mt * 16 + lr;
                #pragma unroll
                for (int nt = 0; nt < 4; nt++) {
                    int gj = j0 + wn * 32 + nt * 8 + lc * 2;
                    float2 v0 = {acc[mt][nt][0], acc[mt][nt][1]};
                    float2 v1 = {acc[mt][nt][2], acc[mt][nt][3]};
                    *(float2*)(Pb + (size_t)(gi    ) * SS + gj) = v0;
                    *(float2*)(Pb + (size_t)(gi + 8) * SS + gj) = v1;
                }
            }
        } else {
            #pragma unroll
            for (int mt = 0; mt < 4; mt++) {
                int gi = i0 + wm * 64 + mt * 16 + lr;
                #pragma unroll
                for (int nt = 0; nt < 4; nt++) {
                    int gj = j0 + wn * 32 + nt * 8 + lc * 2;
                    if (gj     <= gi    ) Pb[(size_t)(gi    ) * SS + gj    ] = acc[mt][nt][0];
                    if (gj + 1 <= gi    ) Pb[(size_t)(gi    ) * SS + gj + 1] = acc[mt][nt][1];
                    if (gj     <= gi + 8) Pb[(size_t)(gi + 8) * SS + gj    ] = acc[mt][nt][2];
                    if (gj + 1 <= gi + 8) Pb[(size_t)(gi + 8) * SS + gj + 1] = acc[mt][nt][3];
                }
            }
        }
    }
}

// ---------------------------------------------------------------------------
// Kernel 4: row softmax, 2 passes, unnormalized tf32(E) + g_inv. (unchanged)
// ---------------------------------------------------------------------------
__global__ void __launch_bounds__(256) softmax_kernel()
{
    const int g = blockIdx.x;
    const int q = g & (SS - 1);
    float* row = g_P + (size_t)g * SS;
    const int len  = q + 1;
    const int len4 = len & ~3;
    const int kend = ((q >> 7) + 1) << 7;

    __shared__ float buf[SS];
    __shared__ float red[8];
    const int tid  = threadIdx.x;
    const int lane = tid & 31, wid = tid >> 5;

    float mx = -3.0e38f;
    for (int i = tid * 4; i < len4; i += 1024) {
        float4 v = *(const float4*)(row + i);
        *(float4*)(buf + i) = v;
        mx = fmaxf(fmaxf(fmaxf(mx, v.x), v.y), fmaxf(v.z, v.w));
    }
    for (int i = len4 + tid; i < len; i += 256) {
        float v = row[i];
        buf[i] = v;
        mx = fmaxf(mx, v);
    }
    #pragma unroll
    for (int o = 16; o > 0; o >>= 1) mx = fmaxf(mx, __shfl_xor_sync(0xffffffffu, mx, o));
    if (lane == 0) red[wid] = mx;
    __syncthreads();
    float m = fmaxf(fmaxf(fmaxf(red[0], red[1]), fmaxf(red[2], red[3])),
                    fmaxf(fmaxf(red[4], red[5]), fmaxf(red[6], red[7])));
    __syncthreads();

    float sm = 0.f;
    for (int i = tid * 4; i < len4; i += 1024) {
        float4 v = *(const float4*)(buf + i);
        v.x = __expf(v.x - m); v.y = __expf(v.y - m);
        v.z = __expf(v.z - m); v.w = __expf(v.w - m);
        sm += (v.x + v.y) + (v.z + v.w);
        v.x = __uint_as_float(f2tf32(v.x));
        v.y = __uint_as_float(f2tf32(v.y));
        v.z = __uint_as_float(f2tf32(v.z));
        v.w = __uint_as_float(f2tf32(v.w));
        *(float4*)(row + i) = v;
    }
    for (int i = len4 + tid; i < len; i += 256) {
        float e = __expf(buf[i] - m);
        sm += e;
        row[i] = __uint_as_float(f2tf32(e));
    }
    #pragma unroll
    for (int o = 16; o > 0; o >>= 1) sm += __shfl_xor_sync(0xffffffffu, sm, o);
    if (lane == 0) red[wid] = sm;
    __syncthreads();
    if (tid == 0) {
        g_inv[g] = 1.0f / (((red[0] + red[1]) + (red[2] + red[3])) +
                           ((red[4] + red[5]) + (red[6] + red[7])));
    }

    for (int i = len + tid; i < kend; i += 256)
        row[i] = 0.0f;
}

// ---------------------------------------------------------------------------
// Kernel 5: out[b] = diag(inv) * (E[b] @ x[b]).  ROUND-15 CONFIG (proven 120us):
// BM=128, BN=128, BK=64; 256 threads, 8 warps 2x4, warp tile 64x32;
// 3-stage cp.async (wait_group(1) slack), single sync, LPT, inv epilogue.
// ---------------------------------------------------------------------------
#define PV_STAGES 3
#define PV_AS 68
#define PV_BS 136
#define PV_STAGE_FLOATS (128 * PV_AS + 64 * PV_BS)   // 17408

__global__ void __launch_bounds__(256, 1) pv_mma_kernel(float* __restrict__ out)
{
    extern __shared__ float sm[];

    const int tid = threadIdx.x;
    const int n0 = blockIdx.x * 128;
    const int m0 = ((int)gridDim.y - 1 - (int)blockIdx.y) * 128;   // LPT
    const int b  = blockIdx.z;

    const float* P  = g_P + (size_t)b * SS * SS;
    const float* Xb = g_x + (size_t)b * SS * DD;
    const int ntiles = (m0 + 128) / 64;     // BK=64 -> >= 2 always

    auto issue_tile = [&](int t) {
        const int stg = t % PV_STAGES;
        float* As = sm + stg * PV_STAGE_FLOATS;
        float* Bs = As + 128 * PV_AS;
        const int kt = t * 64;
        #pragma unroll
        for (int i = 0; i < 8; i++) {            // A: 128x64 = 2048 float4
            int idx = tid + i * 256;
            int r = idx >> 4, c = (idx & 15) * 4;
            const float* src = P + (size_t)(m0 + r) * SS + kt + c;
            uint32_t dst = (uint32_t)__cvta_generic_to_shared(As + r * PV_AS + c);
            asm volatile("cp.async.cg.shared.global [%0], [%1], 16;\n"
                         :: "r"(dst), "l"(src) : "memory");
        }
        #pragma unroll
        for (int i = 0; i < 8; i++) {            // B: 64x128 = 2048 float4
            int idx = tid + i * 256;
            int r = idx >> 5, c = (idx & 31) * 4;
            const float* src = Xb + (size_t)(kt + r) * DD + n0 + c;
            uint32_t dst = (uint32_t)__cvta_generic_to_shared(Bs + r * PV_BS + c);
            asm volatile("cp.async.cg.shared.global [%0], [%1], 16;\n"
                         :: "r"(dst), "l"(src) : "memory");
        }
    };

    #pragma unroll
    for (int t = 0; t < PV_STAGES - 1; t++) {
        if (t < ntiles) issue_tile(t);
        asm volatile("cp.async.commit_group;\n" ::: "memory");
    }

    const int lane = tid & 31, wid = tid >> 5;
    const int wm = wid >> 2, wn = wid & 3;       // 2x4 warps
    const int lr = lane >> 2, lc = lane & 3;

    float acc[4][4][4] = {};                     // warp tile 64x32

    for (int t = 0; t < ntiles; t++) {
        asm volatile("cp.async.wait_group %0;\n" :: "n"(PV_STAGES - 2) : "memory");
        __syncthreads();
        if (t + PV_STAGES - 1 < ntiles) issue_tile(t + PV_STAGES - 1);
        asm volatile("cp.async.commit_group;\n" ::: "memory");

        const int stg = t % PV_STAGES;
        const float* As = sm + stg * PV_STAGE_FLOATS;
        const float* Bs = As + 128 * PV_AS;

        #pragma unroll
        for (int ks = 0; ks < 64; ks += 8) {
            uint32_t afrag[4][4];
            #pragma unroll
            for (int mt = 0; mt < 4; mt++) {
                int mrow = wm * 64 + mt * 16 + lr;
                afrag[mt][0] = __float_as_uint(As[(mrow    ) * PV_AS + ks + lc    ]);
                afrag[mt][1] = __float_as_uint(As[(mrow + 8) * PV_AS + ks + lc    ]);
                afrag[mt][2] = __float_as_uint(As[(mrow    ) * PV_AS + ks + lc + 4]);
                afrag[mt][3] = __float_as_uint(As[(mrow + 8) * PV_AS + ks + lc + 4]);
            }
            uint32_t bfrag[4][2];
            #pragma unroll
            for (int nt = 0; nt < 4; nt++) {
                int ncol = wn * 32 + nt * 8 + lr;
                bfrag[nt][0] = __float_as_uint(Bs[(ks + lc    ) * PV_BS + ncol]);
                bfrag[nt][1] = __float_as_uint(Bs[(ks + lc + 4) * PV_BS + ncol]);
            }
            #pragma unroll
            for (int mt = 0; mt < 4; mt++)
                #pragma unroll
                for (int nt = 0; nt < 4; nt++)
                    mma_tf32(acc[mt][nt], afrag[mt], bfrag[nt]);
        }
    }

    #pragma unroll
    for (int mt = 0; mt < 4; mt++) {
        int m = m0 + wm * 64 + mt * 16 + lr;
        float inv0 = g_inv[b * SS + m];
        float inv1 = g_inv[b * SS + m + 8];
        #pragma unroll
        for (int nt = 0; nt < 4; nt++) {
            int n = n0 + wn * 32 + nt * 8 + lc * 2;
            float2 v0 = {acc[mt][nt][0] * inv0, acc[mt][nt][1] * inv0};
            float2 v1 = {acc[mt][nt][2] * inv1, acc[mt][nt][3] * inv1};
            *(float2*)(out + (size_t)(b * SS + m    ) * DD + n) = v0;
            *(float2*)(out + (size_t)(b * SS + m + 8) * DD + n) = v1;
        }
    }
}

// ---------------------------------------------------------------------------
// Host launch (graph-capturable: kernel launches only)
// ---------------------------------------------------------------------------
extern "C" void kernel_launch(void* const* d_in, const int* in_sizes, int n_in,
                              void* d_out, int out_size)
{
    const float* X  = (const float*)d_in[0];
    const float* Wq = (const float*)d_in[1];
    const float* Wk = (const float*)d_in[2];
    const float* Wv = (const float*)d_in[3];
    const float* Wo = (const float*)d_in[4];
    float* out = (float*)d_out;

    const int pj_smem  = (2 * 64 * PJ_XS + 2 * 64 * PJ_WS) * 4;    // 137,216
    const int mid_smem = (2 * 128 * XO_AS + 2 * 64 * XO_BS) * 4;   // 139,264
    const int pv_smem  = PV_STAGES * PV_STAGE_FLOATS * 4;          // 208,896

    cudaFuncSetAttribute(proj_mma_kernel, cudaFuncAttributeMaxDynamicSharedMemorySize, pj_smem);
    cudaFuncSetAttribute(mid_mma_kernel,  cudaFuncAttributeMaxDynamicSharedMemorySize, mid_smem);
    cudaFuncSetAttribute(pv_mma_kernel,   cudaFuncAttributeMaxDynamicSharedMemorySize, pv_smem);

    proj_mma_kernel<<<dim3(MTOT / 64, 1, 1), 256, pj_smem>>>(X, Wq, Wk, Wv);
    mid_mma_kernel <<<N_XO_CTAS + N_SC_CTAS, 256, mid_smem>>>(Wo);
    softmax_kernel <<<MTOT, 256>>>();
    pv_mma_kernel  <<<dim3(DD / 128, SS / 128, BB), 256, pv_smem>>>(out);
}